// round 6
// baseline (speedup 1.0000x reference)
#include <cuda_runtime.h>

#define NB 4
#define NT 4096
#define ND 64

#define LDA2 260   // stats: expanded A (xT, dup pairs) row stride, 1040B (16B-mult)
#define LDB  128   // stats: encT K-major tile row stride
#define LDP  132   // out: P tile row stride (528B, 16B-mult)
#define LDX2 132   // out: expanded x tile row stride

typedef unsigned long long u64;

// Scratch (device globals: allocation is forbidden)
__device__ float g_encT[NB*ND*NT];                       // [b][d][t]   4 MB
__device__ float g_S[(size_t)NB*NT*NT];                  // [b][j][i] 256 MB
__device__ float g_m[NB*NT];
__device__ float g_rz[NB*NT];

__device__ __forceinline__ void fma2(u64& c, u64 a, u64 b) {
    asm("fma.rn.f32x2 %0, %1, %2, %3;" : "=l"(c) : "l"(a), "l"(b), "l"(c));
}
__device__ __forceinline__ float2 unpack2(u64 v) {
    float2 r; asm("mov.b64 {%0, %1}, %2;" : "=f"(r.x), "=f"(r.y) : "l"(v)); return r;
}

// ---------------------------------------------------------------------------
// Kernel 1: enc = tanh(softmax(x W1 + b1) W2 + b2), written transposed [d][t].
// One warp per row, 8 rows per block; encT staged via smem for 32B writes.
// ---------------------------------------------------------------------------
__global__ void __launch_bounds__(256) mlp_kernel(
    const float* __restrict__ x, const float* __restrict__ W1,
    const float* __restrict__ b1, const float* __restrict__ W2,
    const float* __restrict__ b2)
{
    __shared__ float sW1[64*64];
    __shared__ float sW2[64*64];
    __shared__ float sbuf[8][64];
    __shared__ float senc[64*9];    // [d][t-within-block], stride 9 (conflict-free)
    int tid = threadIdx.x;
    #pragma unroll
    for (int i = tid*4; i < 4096; i += 1024) {
        *(float4*)&sW1[i] = *(const float4*)&W1[i];
        *(float4*)&sW2[i] = *(const float4*)&W2[i];
    }
    int w = tid >> 5, lane = tid & 31;
    int row = blockIdx.x*8 + w;
    const float* xr = x + (size_t)row*64;
    float x0 = xr[lane], x1 = xr[lane+32];
    sbuf[w][lane] = x0; sbuf[w][lane+32] = x1;
    __syncthreads();                        // W1/W2 + sbuf ready
    float a0 = b1[lane], a1 = b1[lane+32];
    #pragma unroll
    for (int d = 0; d < 64; d++) {
        float xv = sbuf[w][d];
        a0 = fmaf(xv, sW1[d*64+lane   ], a0);
        a1 = fmaf(xv, sW1[d*64+lane+32], a1);
    }
    float mm = fmaxf(a0, a1);
    #pragma unroll
    for (int o = 16; o > 0; o >>= 1) mm = fmaxf(mm, __shfl_xor_sync(0xffffffffu, mm, o));
    float e0 = __expf(a0 - mm), e1 = __expf(a1 - mm);
    float ss = e0 + e1;
    #pragma unroll
    for (int o = 16; o > 0; o >>= 1) ss += __shfl_xor_sync(0xffffffffu, ss, o);
    float rs = 1.0f/ss;
    __syncwarp();
    sbuf[w][lane] = e0*rs; sbuf[w][lane+32] = e1*rs;
    __syncwarp();
    float c0 = b2[lane], c1 = b2[lane+32];
    #pragma unroll
    for (int d = 0; d < 64; d++) {
        float hv = sbuf[w][d];
        c0 = fmaf(hv, sW2[d*64+lane   ], c0);
        c1 = fmaf(hv, sW2[d*64+lane+32], c1);
    }
    senc[lane*9 + w]      = tanhf(c0);
    senc[(lane+32)*9 + w] = tanhf(c1);
    __syncthreads();
    if (tid < 64) {
        int rb = blockIdx.x*8;
        int b = rb >> 12, t0 = rb & 4095;
        float v[8];
        #pragma unroll
        for (int q = 0; q < 8; q++) v[q] = senc[tid*9 + q];
        float* dst = &g_encT[((size_t)(b*64 + tid))*4096 + t0];
        *(float4*)dst     = make_float4(v[0], v[1], v[2], v[3]);
        *(float4*)(dst+4) = make_float4(v[4], v[5], v[6], v[7]);
    }
}

// ---------------------------------------------------------------------------
// Kernel 2: S[b,j,i] = x_j . enc_i  (stored raw) + per-j softmax stats (m, 1/Z).
// Block = (b, j-tile 128). A (xT j-tile) transposed+pair-duplicated in smem so
// the inner loop is pure FMA2:  c2[r][cp] += (a,a) * (b_i, b_{i+1}).
// ---------------------------------------------------------------------------
__global__ void __launch_bounds__(256,1) stats_kernel(const float* __restrict__ x)
{
    extern __shared__ float smem[];
    float* sA2 = smem;                // [64 k][LDA2]  expanded xT: [k][2j],[2j+1]
    float* sB  = smem + 64*LDA2;      // [64 k][LDB]   encT i-tile (K-major)
    int tid = threadIdx.x;
    int b  = blockIdx.x >> 5;
    int j0 = (blockIdx.x & 31) * 128;
    const float* xb  = x + (size_t)b*4096*64;
    const float* eTb = g_encT + (size_t)b*64*4096;

    // Transpose + duplicate x j-tile into sA2 (once per block)
    for (int it = tid; it < 2048; it += 256) {
        int j = it >> 4, c4 = (it & 15)*4;
        float4 v = *(const float4*)&xb[(size_t)(j0+j)*64 + c4];
        sA2[(c4+0)*LDA2 + 2*j] = v.x; sA2[(c4+0)*LDA2 + 2*j + 1] = v.x;
        sA2[(c4+1)*LDA2 + 2*j] = v.y; sA2[(c4+1)*LDA2 + 2*j + 1] = v.y;
        sA2[(c4+2)*LDA2 + 2*j] = v.z; sA2[(c4+2)*LDA2 + 2*j + 1] = v.z;
        sA2[(c4+3)*LDA2 + 2*j] = v.w; sA2[(c4+3)*LDA2 + 2*j + 1] = v.w;
    }
    int ty = tid >> 4, tx = tid & 15;
    float m[8], Z[8];
    #pragma unroll
    for (int r = 0; r < 8; r++) { m[r] = -1e30f; Z[r] = 0.0f; }

    for (int itile = 0; itile < 32; ++itile) {
        __syncthreads();
        for (int it = tid; it < 2048; it += 256) {
            int d = it >> 5, c4 = (it & 31)*4;
            *(float4*)&sB[d*LDB + c4] =
                *(const float4*)&eTb[(size_t)d*4096 + itile*128 + c4];
        }
        __syncthreads();
        u64 c2[8][4];
        #pragma unroll
        for (int r = 0; r < 8; r++)
            #pragma unroll
            for (int cp = 0; cp < 4; cp++) c2[r][cp] = 0ull;
        #pragma unroll 8
        for (int k = 0; k < 64; k++) {
            const ulonglong2* pa = (const ulonglong2*)&sA2[k*LDA2 + ty*16];
            ulonglong2 qa0 = pa[0], qa1 = pa[1], qa2 = pa[2], qa3 = pa[3];
            const ulonglong2* pb = (const ulonglong2*)&sB[k*LDB + tx*8];
            ulonglong2 qb0 = pb[0], qb1 = pb[1];
            u64 A[8] = {qa0.x,qa0.y,qa1.x,qa1.y,qa2.x,qa2.y,qa3.x,qa3.y};
            u64 Bv[4] = {qb0.x,qb0.y,qb1.x,qb1.y};
            #pragma unroll
            for (int r = 0; r < 8; r++)
                #pragma unroll
                for (int cp = 0; cp < 4; cp++)
                    fma2(c2[r][cp], A[r], Bv[cp]);
        }
        #pragma unroll
        for (int r = 0; r < 8; r++) {
            float cv[8];
            #pragma unroll
            for (int cp = 0; cp < 4; cp++) {
                float2 f = unpack2(c2[r][cp]);
                cv[2*cp] = f.x; cv[2*cp+1] = f.y;
            }
            // store raw scores
            float* sp = g_S + ((size_t)(b*4096 + j0 + ty*8 + r))*4096
                            + itile*128 + tx*8;
            *(float4*)sp     = make_float4(cv[0], cv[1], cv[2], cv[3]);
            *(float4*)(sp+4) = make_float4(cv[4], cv[5], cv[6], cv[7]);
            // online stats
            float tm = cv[0];
            #pragma unroll
            for (int cc = 1; cc < 8; cc++) tm = fmaxf(tm, cv[cc]);
            #pragma unroll
            for (int o = 1; o < 16; o <<= 1) tm = fmaxf(tm, __shfl_xor_sync(0xffffffffu, tm, o));
            float nm = fmaxf(m[r], tm);
            float ps = 0.0f;
            #pragma unroll
            for (int cc = 0; cc < 8; cc++) ps += __expf(cv[cc] - nm);
            #pragma unroll
            for (int o = 1; o < 16; o <<= 1) ps += __shfl_xor_sync(0xffffffffu, ps, o);
            Z[r] = Z[r]*__expf(m[r] - nm) + ps;
            m[r] = nm;
        }
    }
    if (tx == 0) {
        #pragma unroll
        for (int r = 0; r < 8; r++) {
            int j = j0 + ty*8 + r;
            g_m [b*4096 + j] = m[r];
            g_rz[b*4096 + j] = 1.0f/Z[r];
        }
    }
}

// ---------------------------------------------------------------------------
// Kernel 3: out[i,d] = sum_j exp(S[j,i]-m_j)*rz_j * x[j,d].
// Block = (b, i-tile 128). Reads S tiles (no GEMM1 recompute), exp -> sP,
// GEMM2 with FMA2: accumulators pair along i (sP natural pairs), x duplicated.
// ---------------------------------------------------------------------------
__global__ void __launch_bounds__(256,1) out_kernel(const float* __restrict__ x,
                                                    float* __restrict__ out)
{
    extern __shared__ float smem[];
    float* sP  = smem;                 // [128 j][LDP]  P, i contiguous
    float* sX2 = sP + 128*LDP;         // [128 j][LDX2] x dup-expanded along d
    float* sm_ = sX2 + 128*LDX2;       // [128]
    float* sz_ = sm_ + 128;            // [128]
    int tid = threadIdx.x;
    int b  = blockIdx.x >> 5;
    int i0 = (blockIdx.x & 31) * 128;
    const float* xb = x + (size_t)b*4096*64;
    const float* Sb = g_S + ((size_t)b*4096)*4096;
    int ty = tid >> 4, tx = tid & 15;
    u64 o2[4][4];
    #pragma unroll
    for (int p = 0; p < 4; p++)
        #pragma unroll
        for (int d = 0; d < 4; d++) o2[p][d] = 0ull;

    for (int jt = 0; jt < 32; ++jt) {
        int j0 = jt*128;
        __syncthreads();                               // prev GEMM done
        // x j-tile, duplicated along d
        for (int it = tid; it < 2048; it += 256) {
            int j = it >> 4, c4 = (it & 15)*4;
            float4 v = *(const float4*)&xb[(size_t)(j0+j)*64 + c4];
            float* p = &sX2[j*LDX2 + 2*c4];
            *(float4*)p     = make_float4(v.x, v.x, v.y, v.y);
            *(float4*)(p+4) = make_float4(v.z, v.z, v.w, v.w);
        }
        if (tid < 128) sm_[tid]       = g_m [b*4096 + j0 + tid];
        else           sz_[tid - 128] = g_rz[b*4096 + j0 + tid - 128];
        // load S tile into regs
        float4 s0[8], s1[8];
        #pragma unroll
        for (int r = 0; r < 8; r++) {
            const float* sp = Sb + (size_t)(j0 + ty*8 + r)*4096 + i0 + tx*8;
            s0[r] = *(const float4*)sp;
            s1[r] = *(const float4*)(sp+4);
        }
        __syncthreads();                               // sm_/sz_/sX2 ready
        #pragma unroll
        for (int r = 0; r < 8; r++) {
            float mj = sm_[ty*8 + r], rz = sz_[ty*8 + r];
            float4 p0, p1;
            p0.x = __expf(s0[r].x - mj)*rz; p0.y = __expf(s0[r].y - mj)*rz;
            p0.z = __expf(s0[r].z - mj)*rz; p0.w = __expf(s0[r].w - mj)*rz;
            p1.x = __expf(s1[r].x - mj)*rz; p1.y = __expf(s1[r].y - mj)*rz;
            p1.z = __expf(s1[r].z - mj)*rz; p1.w = __expf(s1[r].w - mj)*rz;
            float* pp = &sP[(ty*8 + r)*LDP + tx*8];
            *(float4*)pp     = p0;
            *(float4*)(pp+4) = p1;
        }
        __syncthreads();                               // sP ready
        #pragma unroll 8
        for (int k = 0; k < 128; k++) {
            const ulonglong2* pa = (const ulonglong2*)&sP[k*LDP + ty*8];
            ulonglong2 qa0 = pa[0], qa1 = pa[1];
            const ulonglong2* pb = (const ulonglong2*)&sX2[k*LDX2 + tx*8];
            ulonglong2 qb0 = pb[0], qb1 = pb[1];
            u64 A[4]  = {qa0.x, qa0.y, qa1.x, qa1.y};   // i-pairs
            u64 Bv[4] = {qb0.x, qb0.y, qb1.x, qb1.y};   // (x,x) per d
            #pragma unroll
            for (int p = 0; p < 4; p++)
                #pragma unroll
                for (int d = 0; d < 4; d++)
                    fma2(o2[p][d], A[p], Bv[d]);
        }
    }
    #pragma unroll
    for (int p = 0; p < 4; p++) {
        float2 f[4];
        #pragma unroll
        for (int d = 0; d < 4; d++) f[d] = unpack2(o2[p][d]);
        int i = i0 + ty*8 + 2*p;
        float* dst = out + ((size_t)(b*4096 + i))*64 + tx*4;
        *(float4*)dst      = make_float4(f[0].x, f[1].x, f[2].x, f[3].x);
        *(float4*)(dst+64) = make_float4(f[0].y, f[1].y, f[2].y, f[3].y);
    }
}

// ---------------------------------------------------------------------------
extern "C" void kernel_launch(void* const* d_in, const int* in_sizes, int n_in,
                              void* d_out, int out_size)
{
    (void)in_sizes; (void)n_in; (void)out_size;
    const float* x  = (const float*)d_in[0];
    const float* W1 = (const float*)d_in[1];
    const float* b1 = (const float*)d_in[2];
    const float* W2 = (const float*)d_in[3];
    const float* b2 = (const float*)d_in[4];
    float* out = (float*)d_out;

    const int SMEM_STATS = (64*LDA2 + 64*LDB) * (int)sizeof(float);           //  99,328 B
    const int SMEM_OUT   = (128*LDP + 128*LDX2 + 256) * (int)sizeof(float);   // 136,192 B
    cudaFuncSetAttribute(stats_kernel, cudaFuncAttributeMaxDynamicSharedMemorySize, SMEM_STATS);
    cudaFuncSetAttribute(out_kernel,   cudaFuncAttributeMaxDynamicSharedMemorySize, SMEM_OUT);

    mlp_kernel<<<2048, 256>>>(x, W1, b1, W2, b2);
    stats_kernel<<<128, 256, SMEM_STATS>>>(x);
    out_kernel<<<128, 256, SMEM_OUT>>>(x, out);
}

// round 7
// speedup vs baseline: 1.5677x; 1.5677x over previous
#include <cuda_runtime.h>

#define NB 4
#define NT 4096
#define ND 64

#define LDA2 260   // stats: expanded A (xT, dup pairs) row stride, 1040B (16B-mult)
#define LDB  128   // stats: encT K-major tile row stride
#define LDP  132   // out: P tile row stride (528B, 16B-mult)
#define LDX2 132   // out: expanded x tile row stride

typedef unsigned long long u64;

// Scratch (device globals: allocation is forbidden)
__device__ float g_encT[NB*ND*NT];                       // [b][d][t]   4 MB
__device__ float g_S[(size_t)NB*NT*NT];                  // [b][j][i] 256 MB
__device__ float g_m[NB*NT];
__device__ float g_rz[NB*NT];

__device__ __forceinline__ void fma2(u64& c, u64 a, u64 b) {
    asm("fma.rn.f32x2 %0, %1, %2, %3;" : "=l"(c) : "l"(a), "l"(b), "l"(c));
}
__device__ __forceinline__ float2 unpack2(u64 v) {
    float2 r; asm("mov.b64 {%0, %1}, %2;" : "=f"(r.x), "=f"(r.y) : "l"(v)); return r;
}

// ---------------------------------------------------------------------------
// Kernel 1: enc = tanh(softmax(x W1 + b1) W2 + b2), written transposed [d][t].
// One warp per row, 8 rows per block; encT staged via smem for 32B writes.
// ---------------------------------------------------------------------------
__global__ void __launch_bounds__(256) mlp_kernel(
    const float* __restrict__ x, const float* __restrict__ W1,
    const float* __restrict__ b1, const float* __restrict__ W2,
    const float* __restrict__ b2)
{
    __shared__ float sW1[64*64];
    __shared__ float sW2[64*64];
    __shared__ float sbuf[8][64];
    __shared__ float senc[64*9];    // [d][t-within-block], stride 9 (conflict-free)
    int tid = threadIdx.x;
    #pragma unroll
    for (int i = tid*4; i < 4096; i += 1024) {
        *(float4*)&sW1[i] = *(const float4*)&W1[i];
        *(float4*)&sW2[i] = *(const float4*)&W2[i];
    }
    int w = tid >> 5, lane = tid & 31;
    int row = blockIdx.x*8 + w;
    const float* xr = x + (size_t)row*64;
    float x0 = xr[lane], x1 = xr[lane+32];
    sbuf[w][lane] = x0; sbuf[w][lane+32] = x1;
    __syncthreads();                        // W1/W2 + sbuf ready
    float a0 = b1[lane], a1 = b1[lane+32];
    #pragma unroll
    for (int d = 0; d < 64; d++) {
        float xv = sbuf[w][d];
        a0 = fmaf(xv, sW1[d*64+lane   ], a0);
        a1 = fmaf(xv, sW1[d*64+lane+32], a1);
    }
    float mm = fmaxf(a0, a1);
    #pragma unroll
    for (int o = 16; o > 0; o >>= 1) mm = fmaxf(mm, __shfl_xor_sync(0xffffffffu, mm, o));
    float e0 = __expf(a0 - mm), e1 = __expf(a1 - mm);
    float ss = e0 + e1;
    #pragma unroll
    for (int o = 16; o > 0; o >>= 1) ss += __shfl_xor_sync(0xffffffffu, ss, o);
    float rs = 1.0f/ss;
    __syncwarp();
    sbuf[w][lane] = e0*rs; sbuf[w][lane+32] = e1*rs;
    __syncwarp();
    float c0 = b2[lane], c1 = b2[lane+32];
    #pragma unroll
    for (int d = 0; d < 64; d++) {
        float hv = sbuf[w][d];
        c0 = fmaf(hv, sW2[d*64+lane   ], c0);
        c1 = fmaf(hv, sW2[d*64+lane+32], c1);
    }
    senc[lane*9 + w]      = tanhf(c0);
    senc[(lane+32)*9 + w] = tanhf(c1);
    __syncthreads();
    if (tid < 64) {
        int rb = blockIdx.x*8;
        int b = rb >> 12, t0 = rb & 4095;
        float v[8];
        #pragma unroll
        for (int q = 0; q < 8; q++) v[q] = senc[tid*9 + q];
        float* dst = &g_encT[((size_t)(b*64 + tid))*4096 + t0];
        *(float4*)dst     = make_float4(v[0], v[1], v[2], v[3]);
        *(float4*)(dst+4) = make_float4(v[4], v[5], v[6], v[7]);
    }
}

// ---------------------------------------------------------------------------
// Kernel 2: S[b,j,i] = x_j . enc_i  (stored raw) + per-j softmax stats (m, 1/Z).
// Block = (b, j-tile 128). A (xT j-tile) transposed+pair-duplicated in smem so
// the inner loop is pure FMA2:  c2[r][cp] += (a,a) * (b_i, b_{i+1}).
// ---------------------------------------------------------------------------
__global__ void __launch_bounds__(256,1) stats_kernel(const float* __restrict__ x)
{
    extern __shared__ float smem[];
    float* sA2 = smem;                // [64 k][LDA2]  expanded xT: [k][2j],[2j+1]
    float* sB  = smem + 64*LDA2;      // [64 k][LDB]   encT i-tile (K-major)
    int tid = threadIdx.x;
    int b  = blockIdx.x >> 5;
    int j0 = (blockIdx.x & 31) * 128;
    const float* xb  = x + (size_t)b*4096*64;
    const float* eTb = g_encT + (size_t)b*64*4096;

    // Transpose + duplicate x j-tile into sA2 (once per block)
    for (int it = tid; it < 2048; it += 256) {
        int j = it >> 4, c4 = (it & 15)*4;
        float4 v = *(const float4*)&xb[(size_t)(j0+j)*64 + c4];
        sA2[(c4+0)*LDA2 + 2*j] = v.x; sA2[(c4+0)*LDA2 + 2*j + 1] = v.x;
        sA2[(c4+1)*LDA2 + 2*j] = v.y; sA2[(c4+1)*LDA2 + 2*j + 1] = v.y;
        sA2[(c4+2)*LDA2 + 2*j] = v.z; sA2[(c4+2)*LDA2 + 2*j + 1] = v.z;
        sA2[(c4+3)*LDA2 + 2*j] = v.w; sA2[(c4+3)*LDA2 + 2*j + 1] = v.w;
    }
    int ty = tid >> 4, tx = tid & 15;
    float m[8], Z[8];
    #pragma unroll
    for (int r = 0; r < 8; r++) { m[r] = -1e30f; Z[r] = 0.0f; }

    for (int itile = 0; itile < 32; ++itile) {
        __syncthreads();
        for (int it = tid; it < 2048; it += 256) {
            int d = it >> 5, c4 = (it & 31)*4;
            *(float4*)&sB[d*LDB + c4] =
                *(const float4*)&eTb[(size_t)d*4096 + itile*128 + c4];
        }
        __syncthreads();
        u64 c2[8][4];
        #pragma unroll
        for (int r = 0; r < 8; r++)
            #pragma unroll
            for (int cp = 0; cp < 4; cp++) c2[r][cp] = 0ull;
        #pragma unroll 8
        for (int k = 0; k < 64; k++) {
            const ulonglong2* pa = (const ulonglong2*)&sA2[k*LDA2 + ty*16];
            ulonglong2 qa0 = pa[0], qa1 = pa[1], qa2 = pa[2], qa3 = pa[3];
            const ulonglong2* pb = (const ulonglong2*)&sB[k*LDB + tx*8];
            ulonglong2 qb0 = pb[0], qb1 = pb[1];
            u64 A[8] = {qa0.x,qa0.y,qa1.x,qa1.y,qa2.x,qa2.y,qa3.x,qa3.y};
            u64 Bv[4] = {qb0.x,qb0.y,qb1.x,qb1.y};
            #pragma unroll
            for (int r = 0; r < 8; r++)
                #pragma unroll
                for (int cp = 0; cp < 4; cp++)
                    fma2(c2[r][cp], A[r], Bv[cp]);
        }
        #pragma unroll
        for (int r = 0; r < 8; r++) {
            float cv[8];
            #pragma unroll
            for (int cp = 0; cp < 4; cp++) {
                float2 f = unpack2(c2[r][cp]);
                cv[2*cp] = f.x; cv[2*cp+1] = f.y;
            }
            // store raw scores
            float* sp = g_S + ((size_t)(b*4096 + j0 + ty*8 + r))*4096
                            + itile*128 + tx*8;
            *(float4*)sp     = make_float4(cv[0], cv[1], cv[2], cv[3]);
            *(float4*)(sp+4) = make_float4(cv[4], cv[5], cv[6], cv[7]);
            // online stats
            float tm = cv[0];
            #pragma unroll
            for (int cc = 1; cc < 8; cc++) tm = fmaxf(tm, cv[cc]);
            #pragma unroll
            for (int o = 1; o < 16; o <<= 1) tm = fmaxf(tm, __shfl_xor_sync(0xffffffffu, tm, o));
            float nm = fmaxf(m[r], tm);
            float ps = 0.0f;
            #pragma unroll
            for (int cc = 0; cc < 8; cc++) ps += __expf(cv[cc] - nm);
            #pragma unroll
            for (int o = 1; o < 16; o <<= 1) ps += __shfl_xor_sync(0xffffffffu, ps, o);
            Z[r] = Z[r]*__expf(m[r] - nm) + ps;
            m[r] = nm;
        }
    }
    if (tx == 0) {
        #pragma unroll
        for (int r = 0; r < 8; r++) {
            int j = j0 + ty*8 + r;
            g_m [b*4096 + j] = m[r];
            g_rz[b*4096 + j] = 1.0f/Z[r];
        }
    }
}

// ---------------------------------------------------------------------------
// Kernel 3: out[i,d] = sum_j exp(S[j,i]-m_j)*rz_j * x[j,d].
// Block = (b, i-tile 128). Reads S tiles (no GEMM1 recompute), exp -> sP,
// GEMM2 with FMA2: accumulators pair along i (sP natural pairs), x duplicated.
// ---------------------------------------------------------------------------
__global__ void __launch_bounds__(256,1) out_kernel(const float* __restrict__ x,
                                                    float* __restrict__ out)
{
    extern __shared__ float smem[];
    float* sP  = smem;                 // [128 j][LDP]  P, i contiguous
    float* sX2 = sP + 128*LDP;         // [128 j][LDX2] x dup-expanded along d
    float* sm_ = sX2 + 128*LDX2;       // [128]
    float* sz_ = sm_ + 128;            // [128]
    int tid = threadIdx.x;
    int b  = blockIdx.x >> 5;
    int i0 = (blockIdx.x & 31) * 128;
    const float* xb = x + (size_t)b*4096*64;
    const float* Sb = g_S + ((size_t)b*4096)*4096;
    int ty = tid >> 4, tx = tid & 15;
    u64 o2[4][4];
    #pragma unroll
    for (int p = 0; p < 4; p++)
        #pragma unroll
        for (int d = 0; d < 4; d++) o2[p][d] = 0ull;

    for (int jt = 0; jt < 32; ++jt) {
        int j0 = jt*128;
        __syncthreads();                               // prev GEMM done
        // x j-tile, duplicated along d
        for (int it = tid; it < 2048; it += 256) {
            int j = it >> 4, c4 = (it & 15)*4;
            float4 v = *(const float4*)&xb[(size_t)(j0+j)*64 + c4];
            float* p = &sX2[j*LDX2 + 2*c4];
            *(float4*)p     = make_float4(v.x, v.x, v.y, v.y);
            *(float4*)(p+4) = make_float4(v.z, v.z, v.w, v.w);
        }
        if (tid < 128) sm_[tid]       = g_m [b*4096 + j0 + tid];
        else           sz_[tid - 128] = g_rz[b*4096 + j0 + tid - 128];
        // load S tile into regs
        float4 s0[8], s1[8];
        #pragma unroll
        for (int r = 0; r < 8; r++) {
            const float* sp = Sb + (size_t)(j0 + ty*8 + r)*4096 + i0 + tx*8;
            s0[r] = *(const float4*)sp;
            s1[r] = *(const float4*)(sp+4);
        }
        __syncthreads();                               // sm_/sz_/sX2 ready
        #pragma unroll
        for (int r = 0; r < 8; r++) {
            float mj = sm_[ty*8 + r], rz = sz_[ty*8 + r];
            float4 p0, p1;
            p0.x = __expf(s0[r].x - mj)*rz; p0.y = __expf(s0[r].y - mj)*rz;
            p0.z = __expf(s0[r].z - mj)*rz; p0.w = __expf(s0[r].w - mj)*rz;
            p1.x = __expf(s1[r].x - mj)*rz; p1.y = __expf(s1[r].y - mj)*rz;
            p1.z = __expf(s1[r].z - mj)*rz; p1.w = __expf(s1[r].w - mj)*rz;
            float* pp = &sP[(ty*8 + r)*LDP + tx*8];
            *(float4*)pp     = p0;
            *(float4*)(pp+4) = p1;
        }
        __syncthreads();                               // sP ready
        #pragma unroll 8
        for (int k = 0; k < 128; k++) {
            const ulonglong2* pa = (const ulonglong2*)&sP[k*LDP + ty*8];
            ulonglong2 qa0 = pa[0], qa1 = pa[1];
            const ulonglong2* pb = (const ulonglong2*)&sX2[k*LDX2 + tx*8];
            ulonglong2 qb0 = pb[0], qb1 = pb[1];
            u64 A[4]  = {qa0.x, qa0.y, qa1.x, qa1.y};   // i-pairs
            u64 Bv[4] = {qb0.x, qb0.y, qb1.x, qb1.y};   // (x,x) per d
            #pragma unroll
            for (int p = 0; p < 4; p++)
                #pragma unroll
                for (int d = 0; d < 4; d++)
                    fma2(o2[p][d], A[p], Bv[d]);
        }
    }
    #pragma unroll
    for (int p = 0; p < 4; p++) {
        float2 f[4];
        #pragma unroll
        for (int d = 0; d < 4; d++) f[d] = unpack2(o2[p][d]);
        int i = i0 + ty*8 + 2*p;
        float* dst = out + ((size_t)(b*4096 + i))*64 + tx*4;
        *(float4*)dst      = make_float4(f[0].x, f[1].x, f[2].x, f[3].x);
        *(float4*)(dst+64) = make_float4(f[0].y, f[1].y, f[2].y, f[3].y);
    }
}

// ---------------------------------------------------------------------------
extern "C" void kernel_launch(void* const* d_in, const int* in_sizes, int n_in,
                              void* d_out, int out_size)
{
    (void)in_sizes; (void)n_in; (void)out_size;
    const float* x  = (const float*)d_in[0];
    const float* W1 = (const float*)d_in[1];
    const float* b1 = (const float*)d_in[2];
    const float* W2 = (const float*)d_in[3];
    const float* b2 = (const float*)d_in[4];
    float* out = (float*)d_out;

    const int SMEM_STATS = (64*LDA2 + 64*LDB) * (int)sizeof(float);           //  99,328 B
    const int SMEM_OUT   = (128*LDP + 128*LDX2 + 256) * (int)sizeof(float);   // 136,192 B
    cudaFuncSetAttribute(stats_kernel, cudaFuncAttributeMaxDynamicSharedMemorySize, SMEM_STATS);
    cudaFuncSetAttribute(out_kernel,   cudaFuncAttributeMaxDynamicSharedMemorySize, SMEM_OUT);

    mlp_kernel<<<2048, 256>>>(x, W1, b1, W2, b2);
    stats_kernel<<<128, 256, SMEM_STATS>>>(x);
    out_kernel<<<128, 256, SMEM_OUT>>>(x, out);
}

// round 9
// speedup vs baseline: 2.5374x; 1.6186x over previous
#include <cuda_runtime.h>
#include <cuda_bf16.h>
#include <stdint.h>

typedef unsigned int u32;
typedef unsigned long long u64;

#define NB 4
#define NT 4096
#define L2E 1.4426950408889634f

// ---- device-global scratch (allocation forbidden) ----
__device__ __align__(128) __nv_bfloat16 g_xHi[NB*NT*64];   // x natural [row][d]
__device__ __align__(128) __nv_bfloat16 g_xLo[NB*NT*64];
__device__ __align__(128) __nv_bfloat16 g_eHi[NB*NT*64];   // enc natural
__device__ __align__(128) __nv_bfloat16 g_eLo[NB*NT*64];
__device__ __align__(128) __nv_bfloat16 g_xTHi[NB*64*NT];  // xT [b][d][t]
__device__ __align__(128) __nv_bfloat16 g_xTLo[NB*64*NT];
__device__ float g_rz[NB*NT];                               // 1/Z_j

__device__ __forceinline__ float ex2f_(float x){
    float r; asm("ex2.approx.ftz.f32 %0, %1;" : "=f"(r) : "f"(x)); return r;
}
__device__ __forceinline__ void mma_bf16(float c[4], u32 a0,u32 a1,u32 a2,u32 a3,
                                         u32 b0,u32 b1){
    asm volatile("mma.sync.aligned.m16n8k16.row.col.f32.bf16.bf16.f32 "
        "{%0,%1,%2,%3}, {%4,%5,%6,%7}, {%8,%9}, {%0,%1,%2,%3};"
        : "+f"(c[0]),"+f"(c[1]),"+f"(c[2]),"+f"(c[3])
        : "r"(a0),"r"(a1),"r"(a2),"r"(a3),"r"(b0),"r"(b1));
}
__device__ __forceinline__ u32 bits2(__nv_bfloat162 v){ return *(u32*)&v; }

#define LDN 68    // padded stride for natural [128][64] bf16 tiles
#define LDT 132   // padded stride for xT [64][128] bf16 tiles

// ---------------------------------------------------------------------------
// Kernel 1: enc = tanh(softmax(x W1 + b1) W2 + b2).
// Emits x/enc natural hi+lo bf16 and xT hi+lo bf16.
// ---------------------------------------------------------------------------
__global__ void __launch_bounds__(256) mlp_kernel(
    const float* __restrict__ x, const float* __restrict__ W1,
    const float* __restrict__ b1, const float* __restrict__ W2,
    const float* __restrict__ b2)
{
    __shared__ float sW1[64*64];
    __shared__ float sW2[64*64];
    __shared__ float sbuf[8][64];
    int tid = threadIdx.x;
    #pragma unroll
    for (int i = tid*4; i < 4096; i += 1024) {
        *(float4*)&sW1[i] = *(const float4*)&W1[i];
        *(float4*)&sW2[i] = *(const float4*)&W2[i];
    }
    int w = tid >> 5, lane = tid & 31;
    int row = blockIdx.x*8 + w;
    const float* xr = x + (size_t)row*64;
    float x0 = xr[lane], x1 = xr[lane+32];
    sbuf[w][lane] = x0; sbuf[w][lane+32] = x1;
    __syncthreads();                         // W1/W2 + all sbuf rows ready
    // natural x hi/lo (pair writes)
    {
        float v0 = sbuf[w][2*lane], v1 = sbuf[w][2*lane+1];
        __nv_bfloat162 h2 = __floats2bfloat162_rn(v0, v1);
        __nv_bfloat162 l2 = __floats2bfloat162_rn(v0 - __bfloat162float(h2.x),
                                                  v1 - __bfloat162float(h2.y));
        ((__nv_bfloat162*)g_xHi)[(size_t)row*32 + lane] = h2;
        ((__nv_bfloat162*)g_xLo)[(size_t)row*32 + lane] = l2;
    }
    // xT hi/lo: thread tid<64 owns dim d=tid, 8 consecutive t's
    if (tid < 64) {
        int rb = blockIdx.x*8;
        int bb = rb >> 12, t0 = rb & 4095;
        __align__(16) __nv_bfloat16 hv[8], lv[8];
        #pragma unroll
        for (int q = 0; q < 8; q++) {
            float v = sbuf[q][tid];
            hv[q] = __float2bfloat16(v);
            lv[q] = __float2bfloat16(v - __bfloat162float(hv[q]));
        }
        *(uint4*)&g_xTHi[((size_t)(bb*64+tid))*4096 + t0] = *(uint4*)hv;
        *(uint4*)&g_xTLo[((size_t)(bb*64+tid))*4096 + t0] = *(uint4*)lv;
    }
    float a0 = b1[lane], a1 = b1[lane+32];
    #pragma unroll
    for (int d = 0; d < 64; d++) {
        float xv = sbuf[w][d];
        a0 = fmaf(xv, sW1[d*64+lane   ], a0);
        a1 = fmaf(xv, sW1[d*64+lane+32], a1);
    }
    float mm = fmaxf(a0, a1);
    #pragma unroll
    for (int o = 16; o > 0; o >>= 1) mm = fmaxf(mm, __shfl_xor_sync(0xffffffffu, mm, o));
    float e0 = __expf(a0 - mm), e1 = __expf(a1 - mm);
    float ss = e0 + e1;
    #pragma unroll
    for (int o = 16; o > 0; o >>= 1) ss += __shfl_xor_sync(0xffffffffu, ss, o);
    float rs = 1.0f/ss;
    __syncthreads();                         // xT cross-warp readers done
    sbuf[w][lane] = e0*rs; sbuf[w][lane+32] = e1*rs;
    __syncwarp();
    float c0 = b2[lane], c1 = b2[lane+32];
    #pragma unroll
    for (int d = 0; d < 64; d++) {
        float hv = sbuf[w][d];
        c0 = fmaf(hv, sW2[d*64+lane   ], c0);
        c1 = fmaf(hv, sW2[d*64+lane+32], c1);
    }
    float t0v = tanhf(c0), t1v = tanhf(c1);
    __syncwarp();
    sbuf[w][lane] = t0v; sbuf[w][lane+32] = t1v;
    __syncwarp();
    {
        float v0 = sbuf[w][2*lane], v1 = sbuf[w][2*lane+1];
        __nv_bfloat162 h2 = __floats2bfloat162_rn(v0, v1);
        __nv_bfloat162 l2 = __floats2bfloat162_rn(v0 - __bfloat162float(h2.x),
                                                  v1 - __bfloat162float(h2.y));
        ((__nv_bfloat162*)g_eHi)[(size_t)row*32 + lane] = h2;
        ((__nv_bfloat162*)g_eLo)[(size_t)row*32 + lane] = l2;
    }
}

// copy a [128][64] bf16 natural tile into padded smem (stride LDN)
__device__ __forceinline__ void cp_nat(__nv_bfloat16* dh, __nv_bfloat16* dl,
                                       const __nv_bfloat16* sh, const __nv_bfloat16* sl,
                                       int tid){
    const u64* ph = (const u64*)sh;
    const u64* pl = (const u64*)sl;
    #pragma unroll
    for (int idx = tid; idx < 2048; idx += 256) {
        int r = idx >> 4, c = idx & 15;
        *(u64*)&dh[r*LDN + c*4] = ph[idx];
        *(u64*)&dl[r*LDN + c*4] = pl[idx];
    }
}

// ---------------------------------------------------------------------------
// Kernel 2: Z_j = sum_i exp(x_j . enc_i); writes 1/Z.
// CTA = (b, j-tile 128). MMA: M=j (A=x j-tile, held in regs), N=i, K=d.
// ---------------------------------------------------------------------------
__global__ void __launch_bounds__(256) stats_kernel()
{
    extern __shared__ __nv_bfloat16 sm[];
    __nv_bfloat16* sXh = sm;                 // [128][LDN]
    __nv_bfloat16* sXl = sXh + 128*LDN;
    __nv_bfloat16* sEh = sXl + 128*LDN;
    __nv_bfloat16* sEl = sEh + 128*LDN;
    int tid = threadIdx.x, w = tid>>5, lane = tid&31;
    int g = lane>>2, t = lane&3;
    int b = blockIdx.x >> 5, j0 = (blockIdx.x & 31)*128;

    cp_nat(sXh, sXl, g_xHi + (size_t)(b*4096+j0)*64,
                     g_xLo + (size_t)(b*4096+j0)*64, tid);
    __syncthreads();
    // hold A fragments (rows j = 16w+g, +8) for all 4 k-steps
    u32 ah[4][4], al[4][4];
    int r0 = w*16 + g;
    #pragma unroll
    for (int kt = 0; kt < 4; kt++) {
        int c0 = kt*16 + t*2;
        ah[kt][0] = *(u32*)&sXh[ r0   *LDN + c0];
        ah[kt][1] = *(u32*)&sXh[(r0+8)*LDN + c0];
        ah[kt][2] = *(u32*)&sXh[ r0   *LDN + c0+8];
        ah[kt][3] = *(u32*)&sXh[(r0+8)*LDN + c0+8];
        al[kt][0] = *(u32*)&sXl[ r0   *LDN + c0];
        al[kt][1] = *(u32*)&sXl[(r0+8)*LDN + c0];
        al[kt][2] = *(u32*)&sXl[ r0   *LDN + c0+8];
        al[kt][3] = *(u32*)&sXl[(r0+8)*LDN + c0+8];
    }
    float Z0 = 0.0f, Z1 = 0.0f;

    for (int it = 0; it < 32; ++it) {
        __syncthreads();                     // prev B reads done
        cp_nat(sEh, sEl, g_eHi + (size_t)(b*4096+it*128)*64,
                         g_eLo + (size_t)(b*4096+it*128)*64, tid);
        __syncthreads();
        #pragma unroll
        for (int half = 0; half < 2; half++) {
            float c[8][4];
            #pragma unroll
            for (int n = 0; n < 8; n++)
                c[n][0]=c[n][1]=c[n][2]=c[n][3]=0.0f;
            #pragma unroll
            for (int kt = 0; kt < 4; kt++) {
                int col = kt*16 + t*2;
                #pragma unroll
                for (int n = 0; n < 8; n++) {
                    int ir = (half*64 + n*8 + g)*LDN + col;
                    u32 bh0 = *(u32*)&sEh[ir],   bh1 = *(u32*)&sEh[ir+8];
                    u32 bl0 = *(u32*)&sEl[ir],   bl1 = *(u32*)&sEl[ir+8];
                    mma_bf16(c[n], ah[kt][0],ah[kt][1],ah[kt][2],ah[kt][3], bh0,bh1);
                    mma_bf16(c[n], ah[kt][0],ah[kt][1],ah[kt][2],ah[kt][3], bl0,bl1);
                    mma_bf16(c[n], al[kt][0],al[kt][1],al[kt][2],al[kt][3], bh0,bh1);
                }
            }
            #pragma unroll
            for (int n = 0; n < 8; n++) {
                Z0 += ex2f_(c[n][0]*L2E) + ex2f_(c[n][1]*L2E);
                Z1 += ex2f_(c[n][2]*L2E) + ex2f_(c[n][3]*L2E);
            }
        }
    }
    Z0 += __shfl_xor_sync(0xffffffffu, Z0, 1);
    Z0 += __shfl_xor_sync(0xffffffffu, Z0, 2);
    Z1 += __shfl_xor_sync(0xffffffffu, Z1, 1);
    Z1 += __shfl_xor_sync(0xffffffffu, Z1, 2);
    if (t == 0) {
        g_rz[b*4096 + j0 + w*16 + g    ] = 1.0f/Z0;
        g_rz[b*4096 + j0 + w*16 + g + 8] = 1.0f/Z1;
    }
}

// ---------------------------------------------------------------------------
// Kernel 3: out[i,d] = sum_j ex2(s_ji*L2E)*rz_j * x[j,d].
// CTA = (b, i-tile 128). MMA1: M=i (A=enc i-tile in regs), N=j, K=d.
// Epilogue p -> bf16 hi/lo fragment regs (no smem!). MMA2: M=i, N=d, K=j,
// A=P (regs), B=xT hi/lo. acc in regs across all 32 j-tiles.
// ---------------------------------------------------------------------------
__global__ void __launch_bounds__(256) out_kernel(float* __restrict__ out)
{
    extern __shared__ __nv_bfloat16 sm[];
    __nv_bfloat16* sEh = sm;                 // [128][LDN] enc i-tile (fixed)
    __nv_bfloat16* sEl = sEh + 128*LDN;
    __nv_bfloat16* sXh = sEl + 128*LDN;      // [128][LDN] x j-tile
    __nv_bfloat16* sXl = sXh + 128*LDN;
    __nv_bfloat16* sTh = sXl + 128*LDN;      // [64][LDT]  xT j-tile
    __nv_bfloat16* sTl = sTh + 64*LDT;
    float* sRZ = (float*)(sTl + 64*LDT);     // [128]
    int tid = threadIdx.x, w = tid>>5, lane = tid&31;
    int g = lane>>2, t = lane&3;
    int b = blockIdx.x >> 5, i0 = (blockIdx.x & 31)*128;

    cp_nat(sEh, sEl, g_eHi + (size_t)(b*4096+i0)*64,
                     g_eLo + (size_t)(b*4096+i0)*64, tid);
    __syncthreads();
    u32 eh[4][4], el[4][4];                  // A1 frags: enc rows i
    int r0 = w*16 + g;
    #pragma unroll
    for (int kt = 0; kt < 4; kt++) {
        int c0 = kt*16 + t*2;
        eh[kt][0] = *(u32*)&sEh[ r0   *LDN + c0];
        eh[kt][1] = *(u32*)&sEh[(r0+8)*LDN + c0];
        eh[kt][2] = *(u32*)&sEh[ r0   *LDN + c0+8];
        eh[kt][3] = *(u32*)&sEh[(r0+8)*LDN + c0+8];
        el[kt][0] = *(u32*)&sEl[ r0   *LDN + c0];
        el[kt][1] = *(u32*)&sEl[(r0+8)*LDN + c0];
        el[kt][2] = *(u32*)&sEl[ r0   *LDN + c0+8];
        el[kt][3] = *(u32*)&sEl[(r0+8)*LDN + c0+8];
    }
    float acc[8][4];
    #pragma unroll
    for (int n = 0; n < 8; n++)
        acc[n][0]=acc[n][1]=acc[n][2]=acc[n][3]=0.0f;

    for (int jt = 0; jt < 32; ++jt) {
        __syncthreads();                     // prev MMA reads of sX/sT done
        cp_nat(sXh, sXl, g_xHi + (size_t)(b*4096+jt*128)*64,
                         g_xLo + (size_t)(b*4096+jt*128)*64, tid);
        {
            #pragma unroll
            for (int idx = tid; idx < 2048; idx += 256) {
                int d = idx >> 5, c = idx & 31;
                const u64* ph = (const u64*)(g_xTHi + ((size_t)(b*64+d))*4096 + jt*128);
                const u64* pl = (const u64*)(g_xTLo + ((size_t)(b*64+d))*4096 + jt*128);
                *(u64*)&sTh[d*LDT + c*4] = ph[c];
                *(u64*)&sTl[d*LDT + c*4] = pl[c];
            }
        }
        if (tid < 128) sRZ[tid] = g_rz[b*4096 + jt*128 + tid];
        __syncthreads();

        #pragma unroll
        for (int half = 0; half < 2; half++) {
            // MMA1: S^T[i][j-half 64]
            float c[8][4];
            #pragma unroll
            for (int n = 0; n < 8; n++)
                c[n][0]=c[n][1]=c[n][2]=c[n][3]=0.0f;
            #pragma unroll
            for (int kt = 0; kt < 4; kt++) {
                int col = kt*16 + t*2;
                #pragma unroll
                for (int n = 0; n < 8; n++) {
                    int jr = (half*64 + n*8 + g)*LDN + col;
                    u32 bh0 = *(u32*)&sXh[jr],  bh1 = *(u32*)&sXh[jr+8];
                    u32 bl0 = *(u32*)&sXl[jr],  bl1 = *(u32*)&sXl[jr+8];
                    mma_bf16(c[n], eh[kt][0],eh[kt][1],eh[kt][2],eh[kt][3], bh0,bh1);
                    mma_bf16(c[n], eh[kt][0],eh[kt][1],eh[kt][2],eh[kt][3], bl0,bl1);
                    mma_bf16(c[n], el[kt][0],el[kt][1],el[kt][2],el[kt][3], bh0,bh1);
                }
            }
            // epilogue: p = ex2(s*L2E)*rz_j -> bf16 hi/lo A2 fragments (in regs)
            u32 H0[8], H1[8], L0[8], L1[8];
            #pragma unroll
            for (int n = 0; n < 8; n++) {
                float rza = sRZ[half*64 + n*8 + t*2];
                float rzb = sRZ[half*64 + n*8 + t*2 + 1];
                float p0 = ex2f_(c[n][0]*L2E)*rza;
                float p1 = ex2f_(c[n][1]*L2E)*rzb;
                float p2 = ex2f_(c[n][2]*L2E)*rza;
                float p3 = ex2f_(c[n][3]*L2E)*rzb;
                __nv_bfloat162 h01 = __floats2bfloat162_rn(p0, p1);
                __nv_bfloat162 l01 = __floats2bfloat162_rn(p0 - __bfloat162float(h01.x),
                                                           p1 - __bfloat162float(h01.y));
                __nv_bfloat162 h23 = __floats2bfloat162_rn(p2, p3);
                __nv_bfloat162 l23 = __floats2bfloat162_rn(p2 - __bfloat162float(h23.x),
                                                           p3 - __bfloat162float(h23.y));
                H0[n] = bits2(h01); L0[n] = bits2(l01);
                H1[n] = bits2(h23); L1[n] = bits2(l23);
            }
            // MMA2: acc[i][d] += P^T(half) * xT(half)
            #pragma unroll
            for (int kt2 = 0; kt2 < 4; kt2++) {
                u32 a0 = H0[2*kt2], a2 = H0[2*kt2+1];
                u32 a1 = H1[2*kt2], a3 = H1[2*kt2+1];
                u32 q0 = L0[2*kt2], q2 = L0[2*kt2+1];
                u32 q1 = L1[2*kt2], q3 = L1[2*kt2+1];
                int col = half*64 + kt2*16 + t*2;
                #pragma unroll
                for (int n = 0; n < 8; n++) {
                    int dr = (n*8 + g)*LDT + col;
                    u32 bh0 = *(u32*)&sTh[dr],  bh1 = *(u32*)&sTh[dr+8];
                    u32 bl0 = *(u32*)&sTl[dr],  bl1 = *(u32*)&sTl[dr+8];
                    mma_bf16(acc[n], a0,a1,a2,a3, bh0,bh1);
                    mma_bf16(acc[n], a0,a1,a2,a3, bl0,bl1);
                    mma_bf16(acc[n], q0,q1,q2,q3, bh0,bh1);
                }
            }
        }
    }
    // store: acc[n][0..1] -> (i=16w+g, d=n*8+t*2), acc[n][2..3] -> row +8
    int i = i0 + 16*w + g;
    #pragma unroll
    for (int n = 0; n < 8; n++) {
        int d = n*8 + t*2;
        *(float2*)&out[((size_t)(b*4096 + i    ))*64 + d] = make_float2(acc[n][0], acc[n][1]);
        *(float2*)&out[((size_t)(b*4096 + i + 8))*64 + d] = make_float2(acc[n][2], acc[n][3]);
    }
}

// ---------------------------------------------------------------------------
extern "C" void kernel_launch(void* const* d_in, const int* in_sizes, int n_in,
                              void* d_out, int out_size)
{
    (void)in_sizes; (void)n_in; (void)out_size;
    const float* x  = (const float*)d_in[0];
    const float* W1 = (const float*)d_in[1];
    const float* b1 = (const float*)d_in[2];
    const float* W2 = (const float*)d_in[3];
    const float* b2 = (const float*)d_in[4];
    float* out = (float*)d_out;

    const int SMEM_STATS = 4*128*LDN*2;                         // 69,632 B
    const int SMEM_OUT   = 4*128*LDN*2 + 2*64*LDT*2 + 512;      // 103,936 B
    cudaFuncSetAttribute(stats_kernel, cudaFuncAttributeMaxDynamicSharedMemorySize, SMEM_STATS);
    cudaFuncSetAttribute(out_kernel,   cudaFuncAttributeMaxDynamicSharedMemorySize, SMEM_OUT);

    mlp_kernel<<<2048, 256>>>(x, W1, b1, W2, b2);
    stats_kernel<<<128, 256, SMEM_STATS>>>();
    out_kernel<<<128, 256, SMEM_OUT>>>(out);
}

// round 10
// speedup vs baseline: 4.4996x; 1.7733x over previous
#include <cuda_runtime.h>
#include <cuda_bf16.h>
#include <stdint.h>

typedef unsigned int u32;
typedef unsigned long long u64;

#define NB 4
#define NT 4096
#define L2E 1.4426950408889634f

#define LDN 72    // natural [128][64] bf16 tiles: 144B rows -> bank 4g+t (conflict-free)
#define LDT 136   // xT [64][128] bf16 tiles: 272B rows -> bank 4g+t (conflict-free)

// ---- device-global scratch (allocation forbidden) ----
__device__ __align__(128) __nv_bfloat16 g_xHi[NB*NT*64];   // x natural [row][d]
__device__ __align__(128) __nv_bfloat16 g_xLo[NB*NT*64];
__device__ __align__(128) __nv_bfloat16 g_eHi[NB*NT*64];   // enc natural
__device__ __align__(128) __nv_bfloat16 g_eLo[NB*NT*64];
__device__ __align__(128) __nv_bfloat16 g_xTHi[NB*64*NT];  // xT [b][d][t]
__device__ __align__(128) __nv_bfloat16 g_xTLo[NB*64*NT];
__device__ float g_rz[NB*NT];                               // 1/Z_j

__device__ __forceinline__ float ex2f_(float x){
    float r; asm("ex2.approx.ftz.f32 %0, %1;" : "=f"(r) : "f"(x)); return r;
}
__device__ __forceinline__ void mma_bf16(float c[4], u32 a0,u32 a1,u32 a2,u32 a3,
                                         u32 b0,u32 b1){
    asm volatile("mma.sync.aligned.m16n8k16.row.col.f32.bf16.bf16.f32 "
        "{%0,%1,%2,%3}, {%4,%5,%6,%7}, {%8,%9}, {%0,%1,%2,%3};"
        : "+f"(c[0]),"+f"(c[1]),"+f"(c[2]),"+f"(c[3])
        : "r"(a0),"r"(a1),"r"(a2),"r"(a3),"r"(b0),"r"(b1));
}
__device__ __forceinline__ u32 bits2(__nv_bfloat162 v){ return *(u32*)&v; }
__device__ __forceinline__ u32 smem_u32(const void* p){
    u32 a; asm("{ .reg .u64 t; cvta.to.shared.u64 t, %1; cvt.u32.u64 %0, t; }"
               : "=r"(a) : "l"(p)); return a;
}
__device__ __forceinline__ void cpa16(u32 dst, const void* src){
    asm volatile("cp.async.cg.shared.global [%0], [%1], 16;" :: "r"(dst), "l"(src));
}
#define CPA_COMMIT() asm volatile("cp.async.commit_group;" ::: "memory")
#define CPA_WAIT1()  asm volatile("cp.async.wait_group 1;" ::: "memory")
#define CPA_WAIT0()  asm volatile("cp.async.wait_group 0;" ::: "memory")

// stage a [128][64] bf16 natural tile (contiguous rows) into padded smem (LDN)
__device__ __forceinline__ void stage_nat(u32 dh, u32 dl,
                                          const __nv_bfloat16* sh,
                                          const __nv_bfloat16* sl, int tid){
    #pragma unroll
    for (int idx = tid; idx < 1024; idx += 256) {
        int r = idx >> 3, c = idx & 7;
        u32 off = (u32)(r*LDN + c*8)*2;
        cpa16(dh + off, sh + r*64 + c*8);
        cpa16(dl + off, sl + r*64 + c*8);
    }
}
// stage a [64][128] bf16 xT tile (row stride 4096) into padded smem (LDT)
__device__ __forceinline__ void stage_xt(u32 dh, u32 dl,
                                         const __nv_bfloat16* sh,
                                         const __nv_bfloat16* sl, int tid){
    #pragma unroll
    for (int idx = tid; idx < 1024; idx += 256) {
        int d = idx >> 4, c = idx & 15;
        u32 off = (u32)(d*LDT + c*8)*2;
        cpa16(dh + off, sh + (size_t)d*4096 + c*8);
        cpa16(dl + off, sl + (size_t)d*4096 + c*8);
    }
}

// ---------------------------------------------------------------------------
// Kernel 1: enc = tanh(softmax(x W1 + b1) W2 + b2).
// 32 rows per block (4 per warp, sequential) to amortize the W1/W2 smem fill.
// Emits x/enc natural hi+lo bf16 and xT hi+lo bf16.
// ---------------------------------------------------------------------------
__global__ void __launch_bounds__(256) mlp_kernel(
    const float* __restrict__ x, const float* __restrict__ W1,
    const float* __restrict__ b1, const float* __restrict__ W2,
    const float* __restrict__ b2)
{
    __shared__ float sW1[64*64];
    __shared__ float sW2[64*64];
    __shared__ float sbuf[8][64];
    int tid = threadIdx.x;
    #pragma unroll
    for (int i = tid*4; i < 4096; i += 1024) {
        *(float4*)&sW1[i] = *(const float4*)&W1[i];
        *(float4*)&sW2[i] = *(const float4*)&W2[i];
    }
    int w = tid >> 5, lane = tid & 31;

    for (int q = 0; q < 4; q++) {
        int row = blockIdx.x*32 + q*8 + w;
        const float* xr = x + (size_t)row*64;
        float x0 = xr[lane], x1 = xr[lane+32];
        sbuf[w][lane] = x0; sbuf[w][lane+32] = x1;
        __syncthreads();                     // W (q=0) + all sbuf rows ready
        // natural x hi/lo (pair writes)
        {
            float v0 = sbuf[w][2*lane], v1 = sbuf[w][2*lane+1];
            __nv_bfloat162 h2 = __floats2bfloat162_rn(v0, v1);
            __nv_bfloat162 l2 = __floats2bfloat162_rn(v0 - __bfloat162float(h2.x),
                                                      v1 - __bfloat162float(h2.y));
            ((__nv_bfloat162*)g_xHi)[(size_t)row*32 + lane] = h2;
            ((__nv_bfloat162*)g_xLo)[(size_t)row*32 + lane] = l2;
        }
        // xT hi/lo: thread tid<64 owns dim d=tid, 8 consecutive t's
        if (tid < 64) {
            int rb = blockIdx.x*32 + q*8;
            int bb = rb >> 12, t0 = rb & 4095;
            __align__(16) __nv_bfloat16 hv[8], lv[8];
            #pragma unroll
            for (int qq = 0; qq < 8; qq++) {
                float v = sbuf[qq][tid];
                hv[qq] = __float2bfloat16(v);
                lv[qq] = __float2bfloat16(v - __bfloat162float(hv[qq]));
            }
            *(uint4*)&g_xTHi[((size_t)(bb*64+tid))*4096 + t0] = *(uint4*)hv;
            *(uint4*)&g_xTLo[((size_t)(bb*64+tid))*4096 + t0] = *(uint4*)lv;
        }
        float a0 = b1[lane], a1 = b1[lane+32];
        #pragma unroll
        for (int d = 0; d < 64; d++) {
            float xv = sbuf[w][d];
            a0 = fmaf(xv, sW1[d*64+lane   ], a0);
            a1 = fmaf(xv, sW1[d*64+lane+32], a1);
        }
        float mm = fmaxf(a0, a1);
        #pragma unroll
        for (int o = 16; o > 0; o >>= 1) mm = fmaxf(mm, __shfl_xor_sync(0xffffffffu, mm, o));
        float e0 = __expf(a0 - mm), e1 = __expf(a1 - mm);
        float ss = e0 + e1;
        #pragma unroll
        for (int o = 16; o > 0; o >>= 1) ss += __shfl_xor_sync(0xffffffffu, ss, o);
        float rs = 1.0f/ss;
        __syncthreads();                     // cross-warp sbuf readers (xT) done
        sbuf[w][lane] = e0*rs; sbuf[w][lane+32] = e1*rs;
        __syncwarp();
        float c0 = b2[lane], c1 = b2[lane+32];
        #pragma unroll
        for (int d = 0; d < 64; d++) {
            float hv = sbuf[w][d];
            c0 = fmaf(hv, sW2[d*64+lane   ], c0);
            c1 = fmaf(hv, sW2[d*64+lane+32], c1);
        }
        float t0v = tanhf(c0), t1v = tanhf(c1);
        __syncwarp();
        sbuf[w][lane] = t0v; sbuf[w][lane+32] = t1v;
        __syncwarp();
        {
            float v0 = sbuf[w][2*lane], v1 = sbuf[w][2*lane+1];
            __nv_bfloat162 h2 = __floats2bfloat162_rn(v0, v1);
            __nv_bfloat162 l2 = __floats2bfloat162_rn(v0 - __bfloat162float(h2.x),
                                                      v1 - __bfloat162float(h2.y));
            ((__nv_bfloat162*)g_eHi)[(size_t)row*32 + lane] = h2;
            ((__nv_bfloat162*)g_eLo)[(size_t)row*32 + lane] = l2;
        }
        __syncwarp();                        // enc pair reads done before next q
    }
}

// ---------------------------------------------------------------------------
// Kernel 2: Z_j = sum_i exp(x_j . enc_i); writes 1/Z.
// CTA = (b, j-tile 128). A = x j-tile (regs). enc i-tiles double-buffered
// via cp.async. 3-pass split-precision bf16 mma.
// ---------------------------------------------------------------------------
__global__ void __launch_bounds__(256) stats_kernel()
{
    extern __shared__ char smc[];
    u32 smb = smem_u32(smc);
    // layout (bytes): xh 0, xl 18432, e buffers: 36864 + buf*36864 (h), +18432 (l)
    const int O_X = 0, O_E = 36864, EBUF = 36864, NATB = 18432;
    int tid = threadIdx.x, w = tid>>5, lane = tid&31;
    int g = lane>>2, t = lane&3;
    int b = blockIdx.x >> 5, j0 = (blockIdx.x & 31)*128;

    stage_nat(smb+O_X, smb+O_X+NATB,
              g_xHi + (size_t)(b*4096+j0)*64,
              g_xLo + (size_t)(b*4096+j0)*64, tid);
    CPA_COMMIT();                                       // G: A tiles
    stage_nat(smb+O_E, smb+O_E+NATB,
              g_eHi + (size_t)(b*4096)*64,
              g_eLo + (size_t)(b*4096)*64, tid);
    CPA_COMMIT();                                       // G: enc tile 0
    CPA_WAIT1();                                        // A tiles ready
    __syncthreads();

    const __nv_bfloat16* sXh = (const __nv_bfloat16*)(smc + O_X);
    const __nv_bfloat16* sXl = (const __nv_bfloat16*)(smc + O_X + NATB);
    u32 ah[4][4], al[4][4];
    int r0 = w*16 + g;
    #pragma unroll
    for (int kt = 0; kt < 4; kt++) {
        int c0 = kt*16 + t*2;
        ah[kt][0] = *(u32*)&sXh[ r0   *LDN + c0];
        ah[kt][1] = *(u32*)&sXh[(r0+8)*LDN + c0];
        ah[kt][2] = *(u32*)&sXh[ r0   *LDN + c0+8];
        ah[kt][3] = *(u32*)&sXh[(r0+8)*LDN + c0+8];
        al[kt][0] = *(u32*)&sXl[ r0   *LDN + c0];
        al[kt][1] = *(u32*)&sXl[(r0+8)*LDN + c0];
        al[kt][2] = *(u32*)&sXl[ r0   *LDN + c0+8];
        al[kt][3] = *(u32*)&sXl[(r0+8)*LDN + c0+8];
    }
    float Z0 = 0.0f, Z1 = 0.0f;

    for (int it = 0; it < 32; ++it) {
        if (it+1 < 32) {
            stage_nat(smb+O_E+((it+1)&1)*EBUF, smb+O_E+((it+1)&1)*EBUF+NATB,
                      g_eHi + (size_t)(b*4096+(it+1)*128)*64,
                      g_eLo + (size_t)(b*4096+(it+1)*128)*64, tid);
            CPA_COMMIT();
            CPA_WAIT1();
        } else {
            CPA_WAIT0();
        }
        __syncthreads();                                // tile `it` visible
        const __nv_bfloat16* sEh = (const __nv_bfloat16*)(smc + O_E + (it&1)*EBUF);
        const __nv_bfloat16* sEl = (const __nv_bfloat16*)(smc + O_E + (it&1)*EBUF + NATB);
        #pragma unroll
        for (int half = 0; half < 2; half++) {
            float c[8][4];
            #pragma unroll
            for (int n = 0; n < 8; n++)
                c[n][0]=c[n][1]=c[n][2]=c[n][3]=0.0f;
            #pragma unroll
            for (int kt = 0; kt < 4; kt++) {
                int col = kt*16 + t*2;
                #pragma unroll
                for (int n = 0; n < 8; n++) {
                    int ir = (half*64 + n*8 + g)*LDN + col;
                    u32 bh0 = *(u32*)&sEh[ir],   bh1 = *(u32*)&sEh[ir+8];
                    u32 bl0 = *(u32*)&sEl[ir],   bl1 = *(u32*)&sEl[ir+8];
                    mma_bf16(c[n], ah[kt][0],ah[kt][1],ah[kt][2],ah[kt][3], bh0,bh1);
                    mma_bf16(c[n], ah[kt][0],ah[kt][1],ah[kt][2],ah[kt][3], bl0,bl1);
                    mma_bf16(c[n], al[kt][0],al[kt][1],al[kt][2],al[kt][3], bh0,bh1);
                }
            }
            #pragma unroll
            for (int n = 0; n < 8; n++) {
                Z0 += ex2f_(c[n][0]*L2E) + ex2f_(c[n][1]*L2E);
                Z1 += ex2f_(c[n][2]*L2E) + ex2f_(c[n][3]*L2E);
            }
        }
        __syncthreads();                                // buffer reads done
    }
    Z0 += __shfl_xor_sync(0xffffffffu, Z0, 1);
    Z0 += __shfl_xor_sync(0xffffffffu, Z0, 2);
    Z1 += __shfl_xor_sync(0xffffffffu, Z1, 1);
    Z1 += __shfl_xor_sync(0xffffffffu, Z1, 2);
    if (t == 0) {
        g_rz[b*4096 + j0 + w*16 + g    ] = 1.0f/Z0;
        g_rz[b*4096 + j0 + w*16 + g + 8] = 1.0f/Z1;
    }
}

// ---------------------------------------------------------------------------
// Kernel 3: out[i,d] = sum_j ex2(s_ji*L2E)*rz_j * x[j,d].
// CTA = (b, i-tile 128). MMA1: M=i (A=enc, regs), N=j, K=d. P passes to MMA2
// entirely in registers. MMA2: M=i, N=d, K=j, B=xT. j-tiles double-buffered.
// ---------------------------------------------------------------------------
__global__ void __launch_bounds__(256) out_kernel(float* __restrict__ out)
{
    extern __shared__ char smc[];
    u32 smb = smem_u32(smc);
    // bytes: enc h 0, l 18432; x bufs 36864 + buf*36864; xT bufs 110592 + buf*34816;
    // rz bufs 180224 + buf*512
    const int O_E = 0, O_X = 36864, O_T = 110592, O_RZ = 180224;
    const int NATB = 18432, XBUF = 36864, TB = 17408, TBUF = 34816;
    int tid = threadIdx.x, w = tid>>5, lane = tid&31;
    int g = lane>>2, t = lane&3;
    int b = blockIdx.x >> 5, i0 = (blockIdx.x & 31)*128;

    stage_nat(smb+O_E, smb+O_E+NATB,
              g_eHi + (size_t)(b*4096+i0)*64,
              g_eLo + (size_t)(b*4096+i0)*64, tid);
    CPA_COMMIT();                                       // G: enc (A) tiles
    // first j-tile group
    stage_nat(smb+O_X, smb+O_X+NATB,
              g_xHi + (size_t)(b*4096)*64,
              g_xLo + (size_t)(b*4096)*64, tid);
    stage_xt(smb+O_T, smb+O_T+TB,
             g_xTHi + ((size_t)b*64)*4096,
             g_xTLo + ((size_t)b*64)*4096, tid);
    if (tid < 32) cpa16(smb+O_RZ + tid*16, g_rz + b*4096 + tid*4);
    CPA_COMMIT();
    CPA_WAIT1();                                        // enc ready
    __syncthreads();

    const __nv_bfloat16* sEh = (const __nv_bfloat16*)(smc + O_E);
    const __nv_bfloat16* sEl = (const __nv_bfloat16*)(smc + O_E + NATB);
    u32 eh[4][4], el[4][4];
    int r0 = w*16 + g;
    #pragma unroll
    for (int kt = 0; kt < 4; kt++) {
        int c0 = kt*16 + t*2;
        eh[kt][0] = *(u32*)&sEh[ r0   *LDN + c0];
        eh[kt][1] = *(u32*)&sEh[(r0+8)*LDN + c0];
        eh[kt][2] = *(u32*)&sEh[ r0   *LDN + c0+8];
        eh[kt][3] = *(u32*)&sEh[(r0+8)*LDN + c0+8];
        el[kt][0] = *(u32*)&sEl[ r0   *LDN + c0];
        el[kt][1] = *(u32*)&sEl[(r0+8)*LDN + c0];
        el[kt][2] = *(u32*)&sEl[ r0   *LDN + c0+8];
        el[kt][3] = *(u32*)&sEl[(r0+8)*LDN + c0+8];
    }
    float acc[8][4];
    #pragma unroll
    for (int n = 0; n < 8; n++)
        acc[n][0]=acc[n][1]=acc[n][2]=acc[n][3]=0.0f;

    for (int jt = 0; jt < 32; ++jt) {
        if (jt+1 < 32) {
            int nb = (jt+1) & 1;
            stage_nat(smb+O_X+nb*XBUF, smb+O_X+nb*XBUF+NATB,
                      g_xHi + (size_t)(b*4096+(jt+1)*128)*64,
                      g_xLo + (size_t)(b*4096+(jt+1)*128)*64, tid);
            stage_xt(smb+O_T+nb*TBUF, smb+O_T+nb*TBUF+TB,
                     g_xTHi + ((size_t)b*64)*4096 + (jt+1)*128,
                     g_xTLo + ((size_t)b*64)*4096 + (jt+1)*128, tid);
            if (tid < 32) cpa16(smb+O_RZ+nb*512 + tid*16,
                                g_rz + b*4096 + (jt+1)*128 + tid*4);
            CPA_COMMIT();
            CPA_WAIT1();
        } else {
            CPA_WAIT0();
        }
        __syncthreads();                                // tile `jt` visible
        int cb = jt & 1;
        const __nv_bfloat16* sXh = (const __nv_bfloat16*)(smc + O_X + cb*XBUF);
        const __nv_bfloat16* sXl = (const __nv_bfloat16*)(smc + O_X + cb*XBUF + NATB);
        const __nv_bfloat16* sTh = (const __nv_bfloat16*)(smc + O_T + cb*TBUF);
        const __nv_bfloat16* sTl = (const __nv_bfloat16*)(smc + O_T + cb*TBUF + TB);
        const float* sRZ = (const float*)(smc + O_RZ + cb*512);

        #pragma unroll
        for (int half = 0; half < 2; half++) {
            // MMA1: S^T[i][j-half 64]
            float c[8][4];
            #pragma unroll
            for (int n = 0; n < 8; n++)
                c[n][0]=c[n][1]=c[n][2]=c[n][3]=0.0f;
            #pragma unroll
            for (int kt = 0; kt < 4; kt++) {
                int col = kt*16 + t*2;
                #pragma unroll
                for (int n = 0; n < 8; n++) {
                    int jr = (half*64 + n*8 + g)*LDN + col;
                    u32 bh0 = *(u32*)&sXh[jr],  bh1 = *(u32*)&sXh[jr+8];
                    u32 bl0 = *(u32*)&sXl[jr],  bl1 = *(u32*)&sXl[jr+8];
                    mma_bf16(c[n], eh[kt][0],eh[kt][1],eh[kt][2],eh[kt][3], bh0,bh1);
                    mma_bf16(c[n], eh[kt][0],eh[kt][1],eh[kt][2],eh[kt][3], bl0,bl1);
                    mma_bf16(c[n], el[kt][0],el[kt][1],el[kt][2],el[kt][3], bh0,bh1);
                }
            }
            // epilogue: p = ex2(s*L2E)*rz_j -> bf16 hi/lo A2 fragments (regs)
            u32 H0[8], H1[8], L0[8], L1[8];
            #pragma unroll
            for (int n = 0; n < 8; n++) {
                float rza = sRZ[half*64 + n*8 + t*2];
                float rzb = sRZ[half*64 + n*8 + t*2 + 1];
                float p0 = ex2f_(c[n][0]*L2E)*rza;
                float p1 = ex2f_(c[n][1]*L2E)*rzb;
                float p2 = ex2f_(c[n][2]*L2E)*rza;
                float p3 = ex2f_(c[n][3]*L2E)*rzb;
                __nv_bfloat162 h01 = __floats2bfloat162_rn(p0, p1);
                __nv_bfloat162 l01 = __floats2bfloat162_rn(p0 - __bfloat162float(h01.x),
                                                           p1 - __bfloat162float(h01.y));
                __nv_bfloat162 h23 = __floats2bfloat162_rn(p2, p3);
                __nv_bfloat162 l23 = __floats2bfloat162_rn(p2 - __bfloat162float(h23.x),
                                                           p3 - __bfloat162float(h23.y));
                H0[n] = bits2(h01); L0[n] = bits2(l01);
                H1[n] = bits2(h23); L1[n] = bits2(l23);
            }
            // MMA2: acc[i][d] += P^T(half) * xT(half)
            #pragma unroll
            for (int kt2 = 0; kt2 < 4; kt2++) {
                u32 a0 = H0[2*kt2], a2 = H0[2*kt2+1];
                u32 a1 = H1[2*kt2], a3 = H1[2*kt2+1];
                u32 q0 = L0[2*kt2], q2 = L0[2*kt2+1];
                u32 q1 = L1[2*kt2], q3 = L1[2*kt2+1];
                int col = half*64 + kt2*16 + t*2;
                #pragma unroll
                for (int n = 0; n < 8; n++) {
                    int dr = (n*8 + g)*LDT + col;
                    u32 bh0 = *(u32*)&sTh[dr],  bh1 = *(u32*)&sTh[dr+8];
                    u32 bl0 = *(u32*)&sTl[dr],  bl1 = *(u32*)&sTl[dr+8];
                    mma_bf16(acc[n], a0,a1,a2,a3, bh0,bh1);
                    mma_bf16(acc[n], a0,a1,a2,a3, bl0,bl1);
                    mma_bf16(acc[n], q0,q1,q2,q3, bh0,bh1);
                }
            }
        }
        __syncthreads();                                // buffer reads done
    }
    // store: acc[n][0..1] -> (i=16w+g, d=n*8+t*2), acc[n][2..3] -> row +8
    int i = i0 + 16*w + g;
    #pragma unroll
    for (int n = 0; n < 8; n++) {
        int d = n*8 + t*2;
        *(float2*)&out[((size_t)(b*4096 + i    ))*64 + d] = make_float2(acc[n][0], acc[n][1]);
        *(float2*)&out[((size_t)(b*4096 + i + 8))*64 + d] = make_float2(acc[n][2], acc[n][3]);
    }
}

// ---------------------------------------------------------------------------
extern "C" void kernel_launch(void* const* d_in, const int* in_sizes, int n_in,
                              void* d_out, int out_size)
{
    (void)in_sizes; (void)n_in; (void)out_size;
    const float* x  = (const float*)d_in[0];
    const float* W1 = (const float*)d_in[1];
    const float* b1 = (const float*)d_in[2];
    const float* W2 = (const float*)d_in[3];
    const float* b2 = (const float*)d_in[4];
    float* out = (float*)d_out;

    const int SMEM_STATS = 110592;   // x(h+l) + 2 x enc(h+l) buffers
    const int SMEM_OUT   = 181248;   // enc + 2x x-buf + 2x xT-buf + 2x rz
    cudaFuncSetAttribute(stats_kernel, cudaFuncAttributeMaxDynamicSharedMemorySize, SMEM_STATS);
    cudaFuncSetAttribute(out_kernel,   cudaFuncAttributeMaxDynamicSharedMemorySize, SMEM_OUT);

    mlp_kernel<<<512, 256>>>(x, W1, b1, W2, b2);
    stats_kernel<<<128, 256, SMEM_STATS>>>();
    out_kernel<<<128, 256, SMEM_OUT>>>(out);
}

// round 14
// speedup vs baseline: 4.8708x; 1.0825x over previous
#include <cuda_runtime.h>
#include <cuda_bf16.h>
#include <stdint.h>

typedef unsigned int u32;
typedef unsigned long long u64;

#define NB 4
#define NT 4096
#define L2E 1.4426950408889634f

#define LDN 72    // natural [128][64] bf16 tiles: 144B rows (16B-mult, conflict-free)
#define LDT 136   // xT [64][128] bf16 tiles: 272B rows (16B-mult, conflict-free)

// ---- device-global scratch (allocation forbidden) ----
__device__ __align__(128) __nv_bfloat16 g_xHi[NB*NT*64];   // x natural [row][d]
__device__ __align__(128) __nv_bfloat16 g_xLo[NB*NT*64];
__device__ __align__(128) __nv_bfloat16 g_eHi[NB*NT*64];   // enc natural
__device__ __align__(128) __nv_bfloat16 g_eLo[NB*NT*64];
__device__ __align__(128) __nv_bfloat16 g_xTHi[NB*64*NT];  // xT [b][d][t]
__device__ __align__(128) __nv_bfloat16 g_xTLo[NB*64*NT];
__device__ float g_rz[NB*NT];                               // 1/Z_j

__device__ __forceinline__ float ex2f_(float x){
    float r; asm("ex2.approx.ftz.f32 %0, %1;" : "=f"(r) : "f"(x)); return r;
}
__device__ __forceinline__ void mma_bf16(float c[4], u32 a0,u32 a1,u32 a2,u32 a3,
                                         u32 b0,u32 b1){
    asm volatile("mma.sync.aligned.m16n8k16.row.col.f32.bf16.bf16.f32 "
        "{%0,%1,%2,%3}, {%4,%5,%6,%7}, {%8,%9}, {%0,%1,%2,%3};"
        : "+f"(c[0]),"+f"(c[1]),"+f"(c[2]),"+f"(c[3])
        : "r"(a0),"r"(a1),"r"(a2),"r"(a3),"r"(b0),"r"(b1));
}
// Non-trans ldmatrix: smem [n][k] row-major chunk -> B fragments directly.
// r0,r1 = {b0,b1} for n-rows [base..base+7]; r2,r3 = for n-rows [base+8..15].
__device__ __forceinline__ void ldm4(u32* r, u32 a){
    asm volatile("ldmatrix.sync.aligned.m8n8.x4.shared.b16 {%0,%1,%2,%3}, [%4];"
        : "=r"(r[0]),"=r"(r[1]),"=r"(r[2]),"=r"(r[3]) : "r"(a));
}
__device__ __forceinline__ u32 bits2(__nv_bfloat162 v){ return *(u32*)&v; }
__device__ __forceinline__ u32 smem_u32(const void* p){
    u32 a; asm("{ .reg .u64 t; cvta.to.shared.u64 t, %1; cvt.u32.u64 %0, t; }"
               : "=r"(a) : "l"(p)); return a;
}
__device__ __forceinline__ void cpa16(u32 dst, const void* src){
    asm volatile("cp.async.cg.shared.global [%0], [%1], 16;" :: "r"(dst), "l"(src));
}
#define CPA_COMMIT() asm volatile("cp.async.commit_group;" ::: "memory")
#define CPA_WAIT1()  asm volatile("cp.async.wait_group 1;" ::: "memory")
#define CPA_WAIT0()  asm volatile("cp.async.wait_group 0;" ::: "memory")

// stage a [128][64] bf16 natural tile (contiguous rows) into padded smem (LDN)
__device__ __forceinline__ void stage_nat(u32 dh, u32 dl,
                                          const __nv_bfloat16* sh,
                                          const __nv_bfloat16* sl, int tid){
    #pragma unroll
    for (int idx = tid; idx < 1024; idx += 256) {
        int r = idx >> 3, c = idx & 7;
        u32 off = (u32)(r*LDN + c*8)*2;
        cpa16(dh + off, sh + r*64 + c*8);
        cpa16(dl + off, sl + r*64 + c*8);
    }
}
// stage a [64][128] bf16 xT tile (row stride 4096) into padded smem (LDT)
__device__ __forceinline__ void stage_xt(u32 dh, u32 dl,
                                         const __nv_bfloat16* sh,
                                         const __nv_bfloat16* sl, int tid){
    #pragma unroll
    for (int idx = tid; idx < 1024; idx += 256) {
        int d = idx >> 4, c = idx & 15;
        u32 off = (u32)(d*LDT + c*8)*2;
        cpa16(dh + off, sh + (size_t)d*4096 + c*8);
        cpa16(dl + off, sl + (size_t)d*4096 + c*8);
    }
}

// ---------------------------------------------------------------------------
// Kernel 1: enc = tanh(softmax(x W1 + b1) W2 + b2).
// 32 rows per block; emits x/enc natural hi+lo bf16 and xT hi+lo bf16.
// ---------------------------------------------------------------------------
__global__ void __launch_bounds__(256) mlp_kernel(
    const float* __restrict__ x, const float* __restrict__ W1,
    const float* __restrict__ b1, const float* __restrict__ W2,
    const float* __restrict__ b2)
{
    __shared__ float sW1[64*64];
    __shared__ float sW2[64*64];
    __shared__ float sbuf[8][64];
    int tid = threadIdx.x;
    #pragma unroll
    for (int i = tid*4; i < 4096; i += 1024) {
        *(float4*)&sW1[i] = *(const float4*)&W1[i];
        *(float4*)&sW2[i] = *(const float4*)&W2[i];
    }
    int w = tid >> 5, lane = tid & 31;

    for (int q = 0; q < 4; q++) {
        int row = blockIdx.x*32 + q*8 + w;
        const float* xr = x + (size_t)row*64;
        float x0 = xr[lane], x1 = xr[lane+32];
        sbuf[w][lane] = x0; sbuf[w][lane+32] = x1;
        __syncthreads();                     // W (q=0) + all sbuf rows ready
        {
            float v0 = sbuf[w][2*lane], v1 = sbuf[w][2*lane+1];
            __nv_bfloat162 h2 = __floats2bfloat162_rn(v0, v1);
            __nv_bfloat162 l2 = __floats2bfloat162_rn(v0 - __bfloat162float(h2.x),
                                                      v1 - __bfloat162float(h2.y));
            ((__nv_bfloat162*)g_xHi)[(size_t)row*32 + lane] = h2;
            ((__nv_bfloat162*)g_xLo)[(size_t)row*32 + lane] = l2;
        }
        if (tid < 64) {
            int rb = blockIdx.x*32 + q*8;
            int bb = rb >> 12, t0 = rb & 4095;
            __align__(16) __nv_bfloat16 hv[8], lv[8];
            #pragma unroll
            for (int qq = 0; qq < 8; qq++) {
                float v = sbuf[qq][tid];
                hv[qq] = __float2bfloat16(v);
                lv[qq] = __float2bfloat16(v - __bfloat162float(hv[qq]));
            }
            *(uint4*)&g_xTHi[((size_t)(bb*64+tid))*4096 + t0] = *(uint4*)hv;
            *(uint4*)&g_xTLo[((size_t)(bb*64+tid))*4096 + t0] = *(uint4*)lv;
        }
        float a0 = b1[lane], a1 = b1[lane+32];
        #pragma unroll
        for (int d = 0; d < 64; d++) {
            float xv = sbuf[w][d];
            a0 = fmaf(xv, sW1[d*64+lane   ], a0);
            a1 = fmaf(xv, sW1[d*64+lane+32], a1);
        }
        float mm = fmaxf(a0, a1);
        #pragma unroll
        for (int o = 16; o > 0; o >>= 1) mm = fmaxf(mm, __shfl_xor_sync(0xffffffffu, mm, o));
        float e0 = __expf(a0 - mm), e1 = __expf(a1 - mm);
        float ss = e0 + e1;
        #pragma unroll
        for (int o = 16; o > 0; o >>= 1) ss += __shfl_xor_sync(0xffffffffu, ss, o);
        float rs = 1.0f/ss;
        __syncthreads();                     // cross-warp sbuf readers (xT) done
        sbuf[w][lane] = e0*rs; sbuf[w][lane+32] = e1*rs;
        __syncwarp();
        float c0 = b2[lane], c1 = b2[lane+32];
        #pragma unroll
        for (int d = 0; d < 64; d++) {
            float hv = sbuf[w][d];
            c0 = fmaf(hv, sW2[d*64+lane   ], c0);
            c1 = fmaf(hv, sW2[d*64+lane+32], c1);
        }
        float t0v = tanhf(c0), t1v = tanhf(c1);
        __syncwarp();
        sbuf[w][lane] = t0v; sbuf[w][lane+32] = t1v;
        __syncwarp();
        {
            float v0 = sbuf[w][2*lane], v1 = sbuf[w][2*lane+1];
            __nv_bfloat162 h2 = __floats2bfloat162_rn(v0, v1);
            __nv_bfloat162 l2 = __floats2bfloat162_rn(v0 - __bfloat162float(h2.x),
                                                      v1 - __bfloat162float(h2.y));
            ((__nv_bfloat162*)g_eHi)[(size_t)row*32 + lane] = h2;
            ((__nv_bfloat162*)g_eLo)[(size_t)row*32 + lane] = l2;
        }
        __syncwarp();
    }
}

// ---------------------------------------------------------------------------
// Kernel 2: Z_j = sum_i exp(x_j . enc_i); writes 1/Z.
// CTA = (b, j-tile 128). A = x j-tile (regs). B via ldmatrix.x4.
// ---------------------------------------------------------------------------
__global__ void __launch_bounds__(256) stats_kernel()
{
    extern __shared__ char smc[];
    u32 smb = smem_u32(smc);
    const int O_X = 0, O_E = 36864, EBUF = 36864, NATB = 18432;
    int tid = threadIdx.x, w = tid>>5, lane = tid&31;
    int g = lane>>2, t = lane&3;
    int b = blockIdx.x >> 5, j0 = (blockIdx.x & 31)*128;
    // ldmatrix per-lane address pieces
    int row_l  = ((lane>>4)<<3) | (lane&7);
    int koff_l = ((lane>>3)&1)<<3;
    u32 lbaseN = (u32)(row_l*LDN + koff_l)*2;

    stage_nat(smb+O_X, smb+O_X+NATB,
              g_xHi + (size_t)(b*4096+j0)*64,
              g_xLo + (size_t)(b*4096+j0)*64, tid);
    CPA_COMMIT();                                       // G: A tiles
    stage_nat(smb+O_E, smb+O_E+NATB,
              g_eHi + (size_t)(b*4096)*64,
              g_eLo + (size_t)(b*4096)*64, tid);
    CPA_COMMIT();                                       // G: enc tile 0
    CPA_WAIT1();                                        // A tiles ready
    __syncthreads();

    const __nv_bfloat16* sXh = (const __nv_bfloat16*)(smc + O_X);
    const __nv_bfloat16* sXl = (const __nv_bfloat16*)(smc + O_X + NATB);
    u32 ah[4][4], al[4][4];
    int r0 = w*16 + g;
    #pragma unroll
    for (int kt = 0; kt < 4; kt++) {
        int c0 = kt*16 + t*2;
        ah[kt][0] = *(u32*)&sXh[ r0   *LDN + c0];
        ah[kt][1] = *(u32*)&sXh[(r0+8)*LDN + c0];
        ah[kt][2] = *(u32*)&sXh[ r0   *LDN + c0+8];
        ah[kt][3] = *(u32*)&sXh[(r0+8)*LDN + c0+8];
        al[kt][0] = *(u32*)&sXl[ r0   *LDN + c0];
        al[kt][1] = *(u32*)&sXl[(r0+8)*LDN + c0];
        al[kt][2] = *(u32*)&sXl[ r0   *LDN + c0+8];
        al[kt][3] = *(u32*)&sXl[(r0+8)*LDN + c0+8];
    }
    float Z0 = 0.0f, Z1 = 0.0f;

    for (int it = 0; it < 32; ++it) {
        if (it+1 < 32) {
            stage_nat(smb+O_E+((it+1)&1)*EBUF, smb+O_E+((it+1)&1)*EBUF+NATB,
                      g_eHi + (size_t)(b*4096+(it+1)*128)*64,
                      g_eLo + (size_t)(b*4096+(it+1)*128)*64, tid);
            CPA_COMMIT();
            CPA_WAIT1();
        } else {
            CPA_WAIT0();
        }
        __syncthreads();                                // tile `it` visible
        u32 eb = smb + O_E + (it&1)*EBUF + lbaseN;
        #pragma unroll
        for (int half = 0; half < 2; half++) {
            float c[8][4];
            #pragma unroll
            for (int n = 0; n < 8; n++)
                c[n][0]=c[n][1]=c[n][2]=c[n][3]=0.0f;
            #pragma unroll
            for (int kt = 0; kt < 4; kt++) {
                u32 BH[16], BL[16];
                #pragma unroll
                for (int nbp = 0; nbp < 4; nbp++) {
                    u32 aH = eb + (u32)(((half*64 + nbp*16)*LDN + kt*16)*2);
                    ldm4(BH + nbp*4, aH);
                    ldm4(BL + nbp*4, aH + NATB);
                }
                #pragma unroll
                for (int n = 0; n < 8; n++) {
                    u32 ix = (n>>1)*4 + (n&1)*2;
                    mma_bf16(c[n], ah[kt][0],ah[kt][1],ah[kt][2],ah[kt][3], BH[ix],BH[ix+1]);
                    mma_bf16(c[n], ah[kt][0],ah[kt][1],ah[kt][2],ah[kt][3], BL[ix],BL[ix+1]);
                    mma_bf16(c[n], al[kt][0],al[kt][1],al[kt][2],al[kt][3], BH[ix],BH[ix+1]);
                }
            }
            #pragma unroll
            for (int n = 0; n < 8; n++) {
                Z0 += ex2f_(c[n][0]*L2E) + ex2f_(c[n][1]*L2E);
                Z1 += ex2f_(c[n][2]*L2E) + ex2f_(c[n][3]*L2E);
            }
        }
        __syncthreads();                                // buffer reads done
    }
    Z0 += __shfl_xor_sync(0xffffffffu, Z0, 1);
    Z0 += __shfl_xor_sync(0xffffffffu, Z0, 2);
    Z1 += __shfl_xor_sync(0xffffffffu, Z1, 1);
    Z1 += __shfl_xor_sync(0xffffffffu, Z1, 2);
    if (t == 0) {
        g_rz[b*4096 + j0 + w*16 + g    ] = 1.0f/Z0;
        g_rz[b*4096 + j0 + w*16 + g + 8] = 1.0f/Z1;
    }
}

// ---------------------------------------------------------------------------
// Kernel 3: out[i,d] = sum_j ex2(s_ji*L2E)*rz_j * x[j,d].
// CTA = (b, i-tile 128). MMA1 B and MMA2 B via ldmatrix.x4; P stays in regs.
// ---------------------------------------------------------------------------
__global__ void __launch_bounds__(256) out_kernel(float* __restrict__ out)
{
    extern __shared__ char smc[];
    u32 smb = smem_u32(smc);
    const int O_E = 0, O_X = 36864, O_T = 110592, O_RZ = 180224;
    const int NATB = 18432, XBUF = 36864, TB = 17408, TBUF = 34816;
    int tid = threadIdx.x, w = tid>>5, lane = tid&31;
    int g = lane>>2, t = lane&3;
    int b = blockIdx.x >> 5, i0 = (blockIdx.x & 31)*128;
    int row_l  = ((lane>>4)<<3) | (lane&7);
    int koff_l = ((lane>>3)&1)<<3;
    u32 lbaseN = (u32)(row_l*LDN + koff_l)*2;
    u32 lbaseT = (u32)(row_l*LDT + koff_l)*2;

    stage_nat(smb+O_E, smb+O_E+NATB,
              g_eHi + (size_t)(b*4096+i0)*64,
              g_eLo + (size_t)(b*4096+i0)*64, tid);
    CPA_COMMIT();                                       // G: enc (A) tiles
    stage_nat(smb+O_X, smb+O_X+NATB,
              g_xHi + (size_t)(b*4096)*64,
              g_xLo + (size_t)(b*4096)*64, tid);
    stage_xt(smb+O_T, smb+O_T+TB,
             g_xTHi + ((size_t)b*64)*4096,
             g_xTLo + ((size_t)b*64)*4096, tid);
    if (tid < 32) cpa16(smb+O_RZ + tid*16, g_rz + b*4096 + tid*4);
    CPA_COMMIT();
    CPA_WAIT1();                                        // enc ready
    __syncthreads();

    const __nv_bfloat16* sEh = (const __nv_bfloat16*)(smc + O_E);
    const __nv_bfloat16* sEl = (const __nv_bfloat16*)(smc + O_E + NATB);
    u32 eh[4][4], el[4][4];
    int r0 = w*16 + g;
    #pragma unroll
    for (int kt = 0; kt < 4; kt++) {
        int c0 = kt*16 + t*2;
        eh[kt][0] = *(u32*)&sEh[ r0   *LDN + c0];
        eh[kt][1] = *(u32*)&sEh[(r0+8)*LDN + c0];
        eh[kt][2] = *(u32*)&sEh[ r0   *LDN + c0+8];
        eh[kt][3] = *(u32*)&sEh[(r0+8)*LDN + c0+8];
        el[kt][0] = *(u32*)&sEl[ r0   *LDN + c0];
        el[kt][1] = *(u32*)&sEl[(r0+8)*LDN + c0];
        el[kt][2] = *(u32*)&sEl[ r0   *LDN + c0+8];
        el[kt][3] = *(u32*)&sEl[(r0+8)*LDN + c0+8];
    }
    float acc[8][4];
    #pragma unroll
    for (int n = 0; n < 8; n++)
        acc[n][0]=acc[n][1]=acc[n][2]=acc[n][3]=0.0f;

    for (int jt = 0; jt < 32; ++jt) {
        if (jt+1 < 32) {
            int nb = (jt+1) & 1;
            stage_nat(smb+O_X+nb*XBUF, smb+O_X+nb*XBUF+NATB,
                      g_xHi + (size_t)(b*4096+(jt+1)*128)*64,
                      g_xLo + (size_t)(b*4096+(jt+1)*128)*64, tid);
            stage_xt(smb+O_T+nb*TBUF, smb+O_T+nb*TBUF+TB,
                     g_xTHi + ((size_t)b*64)*4096 + (jt+1)*128,
                     g_xTLo + ((size_t)b*64)*4096 + (jt+1)*128, tid);
            if (tid < 32) cpa16(smb+O_RZ+nb*512 + tid*16,
                                g_rz + b*4096 + (jt+1)*128 + tid*4);
            CPA_COMMIT();
            CPA_WAIT1();
        } else {
            CPA_WAIT0();
        }
        __syncthreads();                                // tile `jt` visible
        int cb = jt & 1;
        u32 xb = smb + O_X + cb*XBUF + lbaseN;
        u32 tb = smb + O_T + cb*TBUF + lbaseT;
        const float* sRZ = (const float*)(smc + O_RZ + cb*512);

        #pragma unroll
        for (int half = 0; half < 2; half++) {
            // MMA1: S^T[i][j-half 64]
            float c[8][4];
            #pragma unroll
            for (int n = 0; n < 8; n++)
                c[n][0]=c[n][1]=c[n][2]=c[n][3]=0.0f;
            #pragma unroll
            for (int kt = 0; kt < 4; kt++) {
                u32 BH[16], BL[16];
                #pragma unroll
                for (int nbp = 0; nbp < 4; nbp++) {
                    u32 aH = xb + (u32)(((half*64 + nbp*16)*LDN + kt*16)*2);
                    ldm4(BH + nbp*4, aH);
                    ldm4(BL + nbp*4, aH + NATB);
                }
                #pragma unroll
                for (int n = 0; n < 8; n++) {
                    u32 ix = (n>>1)*4 + (n&1)*2;
                    mma_bf16(c[n], eh[kt][0],eh[kt][1],eh[kt][2],eh[kt][3], BH[ix],BH[ix+1]);
                    mma_bf16(c[n], eh[kt][0],eh[kt][1],eh[kt][2],eh[kt][3], BL[ix],BL[ix+1]);
                    mma_bf16(c[n], el[kt][0],el[kt][1],el[kt][2],el[kt][3], BH[ix],BH[ix+1]);
                }
            }
            // epilogue: p = ex2(s*L2E)*rz_j -> bf16 hi/lo A2 fragments (regs)
            u32 H0[8], H1[8], L0[8], L1[8];
            #pragma unroll
            for (int n = 0; n < 8; n++) {
                float rza = sRZ[half*64 + n*8 + t*2];
                float rzb = sRZ[half*64 + n*8 + t*2 + 1];
                float p0 = ex2f_(c[n][0]*L2E)*rza;
                float p1 = ex2f_(c[n][1]*L2E)*rzb;
                float p2 = ex2f_(c[n][2]*L2E)*rza;
                float p3 = ex2f_(c[n][3]*L2E)*rzb;
                __nv_bfloat162 h01 = __floats2bfloat162_rn(p0, p1);
                __nv_bfloat162 l01 = __floats2bfloat162_rn(p0 - __bfloat162float(h01.x),
                                                           p1 - __bfloat162float(h01.y));
                __nv_bfloat162 h23 = __floats2bfloat162_rn(p2, p3);
                __nv_bfloat162 l23 = __floats2bfloat162_rn(p2 - __bfloat162float(h23.x),
                                                           p3 - __bfloat162float(h23.y));
                H0[n] = bits2(h01); L0[n] = bits2(l01);
                H1[n] = bits2(h23); L1[n] = bits2(l23);
            }
            // MMA2: acc[i][d] += P^T(half) * xT(half)
            #pragma unroll
            for (int kt2 = 0; kt2 < 4; kt2++) {
                u32 a0 = H0[2*kt2], a2 = H0[2*kt2+1];
                u32 a1 = H1[2*kt2], a3 = H1[2*kt2+1];
                u32 q0 = L0[2*kt2], q2 = L0[2*kt2+1];
                u32 q1 = L1[2*kt2], q3 = L1[2*kt2+1];
                u32 TH[16], TL[16];
                #pragma unroll
                for (int nbp = 0; nbp < 4; nbp++) {
                    u32 aT = tb + (u32)((nbp*16*LDT + half*64 + kt2*16)*2);
                    ldm4(TH + nbp*4, aT);
                    ldm4(TL + nbp*4, aT + TB);
                }
                #pragma unroll
                for (int n = 0; n < 8; n++) {
                    u32 ix = (n>>1)*4 + (n&1)*2;
                    mma_bf16(acc[n], a0,a1,a2,a3, TH[ix],TH[ix+1]);
                    mma_bf16(acc[n], a0,a1,a2,a3, TL[ix],TL[ix+1]);
                    mma_bf16(acc[n], q0,q1,q2,q3, TH[ix],TH[ix+1]);
                }
            }
        }
        __syncthreads();                                // buffer reads done
    }
    // store: acc[n][0..1] -> (i=16w+g, d=n*8+t*2), acc[n][2..3] -> row +8
    int i = i0 + 16*w + g;
    #pragma unroll
    for (int n = 0; n < 8; n++) {
        int d = n*8 + t*2;
        *(float2*)&out[((size_t)(b*4096 + i    ))*64 + d] = make_float2(acc[n][0], acc[n][1]);
        *(float2*)&out[((size_t)(b*4096 + i + 8))*64 + d] = make_float2(acc[n][2], acc[n][3]);
    }
}

// ---------------------------------------------------------------------------
extern "C" void kernel_launch(void* const* d_in, const int* in_sizes, int n_in,
                              void* d_out, int out_size)
{
    (void)in_sizes; (void)n_in; (void)out_size;
    const float* x  = (const float*)d_in[0];
    const float* W1 = (const float*)d_in[1];
    const float* b1 = (const float*)d_in[2];
    const float* W2 = (const float*)d_in[3];
    const float* b2 = (const float*)d_in[4];
    float* out = (float*)d_out;

    const int SMEM_STATS = 110592;   // x(h+l) + 2 x enc(h+l) buffers
    const int SMEM_OUT   = 181248;   // enc + 2x x-buf + 2x xT-buf + 2x rz
    cudaFuncSetAttribute(stats_kernel, cudaFuncAttributeMaxDynamicSharedMemorySize, SMEM_STATS);
    cudaFuncSetAttribute(out_kernel,   cudaFuncAttributeMaxDynamicSharedMemorySize, SMEM_OUT);

    mlp_kernel<<<512, 256>>>(x, W1, b1, W2, b2);
    stats_kernel<<<128, 256, SMEM_STATS>>>();
    out_kernel<<<128, 256, SMEM_OUT>>>(out);
}